// round 11
// baseline (speedup 1.0000x reference)
#include <cuda_runtime.h>

// CutStripes: out[b, :, t, :] = x[perm[b], :, t, :] if t falls inside any of 4
// stripes [bgn[b,s], bgn[b,s]+distance[b,s]), else x[b, :, t, :].
// Shapes: B=128, C=1, T=2048, F=128, STRIPES=4.
//
// R11: DRAM page-locality experiment. 16 rows (8 KB contiguous) per warp,
// processed as two internal batches of 8 to keep regs ~32 / occ ~80%.
// Halves the number of concurrent DRAM streams vs 8-row groups and doubles
// sequential run length per bank -> better row-buffer hit rate. All other
// choices are the measured-best from R2-R10 (128-bit accesses, plain stores,
// one-shot launch, all-int indexing). One ballot covers 16 rows x 4 stripes:
// lane l checks row l>>1, stripes 2(l&1) and 2(l&1)+1; row r striped iff
// (m >> 2r) & 3.

#define T_DIM         2048
#define F4            32        // 128 floats / 4
#define STRIPES       4
#define ROWS_PER_WARP 16
#define BATCH         8
#define WARPS_PER_BLK 8

__global__ __launch_bounds__(256) void cutstripes_kernel(
    const float4* __restrict__ x,
    const int*    __restrict__ perm,
    const int*    __restrict__ bgn,
    const int*    __restrict__ dist,
    float4*       __restrict__ out)
{
    const int warp = (blockIdx.x * blockDim.x + threadIdx.x) >> 5;  // group id
    const int lane = threadIdx.x & 31;

    // Each group = 16 consecutive t rows of one batch b (128 groups per batch).
    const int b  = warp >> 7;
    const int t0 = (warp & 127) * ROWS_PER_WARP;

    // Lane l: row r = l>>1, stripe pair sp = (l&1)*2. One ballot, 2 bits/row.
    const int r_chk = lane >> 1;
    const int sp    = (lane & 1) * 2;
    const int lo0 = __ldg(&bgn[b * STRIPES + sp]);
    const int hi0 = lo0 + __ldg(&dist[b * STRIPES + sp]);
    const int lo1 = __ldg(&bgn[b * STRIPES + sp + 1]);
    const int hi1 = lo1 + __ldg(&dist[b * STRIPES + sp + 1]);
    const int t_chk = t0 + r_chk;
    const bool in_stripe = ((t_chk >= lo0) && (t_chk < hi0)) ||
                           ((t_chk >= lo1) && (t_chk < hi1));
    const unsigned m = __ballot_sync(0xFFFFFFFFu, in_stripe);
    const int pb = __ldg(&perm[b]);

    const int dst_base = ((b << 11) | t0) * F4 + lane;

    // Two batches of 8: keeps live float4s at 8 (regs ~32) while the warp's
    // total address footprint stays 8 KB contiguous for DRAM page locality.
    #pragma unroll
    for (int h = 0; h < ROWS_PER_WARP / BATCH; h++) {
        const int rbase = h * BATCH;

        float4 v[BATCH];
        #pragma unroll
        for (int r = 0; r < BATCH; r++) {
            const int row = rbase + r;
            const int src = ((m >> (2 * row)) & 3) ? pb : b;
            const int src_idx = ((src << 11) | (t0 + row)) * F4 + lane;
            v[r] = x[src_idx];
        }

        #pragma unroll
        for (int r = 0; r < BATCH; r++) {
            out[dst_base + (rbase + r) * F4] = v[r];
        }
    }
}

extern "C" void kernel_launch(void* const* d_in, const int* in_sizes, int n_in,
                              void* d_out, int out_size)
{
    const float4* x    = (const float4*)d_in[0];   // (128,1,2048,128) fp32
    const int*    perm = (const int*)   d_in[1];   // (128,)
    const int*    bgn  = (const int*)   d_in[2];   // (128,4)
    const int*    dist = (const int*)   d_in[3];   // (128,4)
    float4*       out  = (float4*)d_out;

    const int groups = 128 * T_DIM / ROWS_PER_WARP;   // 16384
    const int blocks = groups / WARPS_PER_BLK;        // 2048

    cutstripes_kernel<<<blocks, 256>>>(x, perm, bgn, dist, out);
}

// round 12
// speedup vs baseline: 1.0014x; 1.0014x over previous
#include <cuda_runtime.h>

// CutStripes: out[b, :, t, :] = x[perm[b], :, t, :] if t falls inside any of 4
// stripes [bgn[b,s], bgn[b,s]+distance[b,s]), else x[b, :, t, :].
// Shapes: B=128, C=1, T=2048, F=128, STRIPES=4.
//
// R12: converged R7 structure (8 rows/warp, one-shot 4096 blocks, front-batched
// LDG.128, plain stores, all-int indexing) + final micro-probe: __ldcs
// streaming loads (evict-first) for the touch-once read stream. Everything
// else measured across R2-R11:
//   - 128-bit optimal (256-bit regressed), MLP non-binding, persistent grid
//     regressed, st.cs neutral, 16-row page groups neutral.
// Kernel sits at the mixed-R/W HBM ceiling: 268 MB / 38.4us = 7.0 TB/s
// combined = 87% of 8 TB/s spec.

#define T_DIM         2048
#define F4            32        // 128 floats / 4
#define STRIPES       4
#define ROWS_PER_WARP 8
#define WARPS_PER_BLK 8

__global__ __launch_bounds__(256) void cutstripes_kernel(
    const float4* __restrict__ x,
    const int*    __restrict__ perm,
    const int*    __restrict__ bgn,
    const int*    __restrict__ dist,
    float4*       __restrict__ out)
{
    const int warp = (blockIdx.x * blockDim.x + threadIdx.x) >> 5;  // group id
    const int lane = threadIdx.x & 31;

    // Each group = 8 consecutive t rows of one batch b (256 groups per batch).
    const int b  = warp >> 8;
    const int t0 = (warp & 255) * ROWS_PER_WARP;

    // Lane l checks row k=l>>2, stripe s=l&3 -> one ballot covers all 8 rows.
    const int k = lane >> 2;
    const int s = lane & 3;
    const int lo = __ldg(&bgn[b * STRIPES + s]);
    const int hi = lo + __ldg(&dist[b * STRIPES + s]);
    const bool in_stripe = ((t0 + k) >= lo) && ((t0 + k) < hi);
    const unsigned m = __ballot_sync(0xFFFFFFFFu, in_stripe);
    const int pb = __ldg(&perm[b]);

    // 8 independent streaming LDG.128 (evict-first: read stream is touch-once).
    float4 v[ROWS_PER_WARP];
    #pragma unroll
    for (int r = 0; r < ROWS_PER_WARP; r++) {
        const int src = ((m >> (4 * r)) & 0xF) ? pb : b;
        const int src_idx = ((src << 11) | (t0 + r)) * F4 + lane;
        v[r] = __ldcs(&x[src_idx]);
    }

    // 8 coalesced STG.128 (plain write-back; st.cs measured neutral in R4).
    const int dst_base = ((b << 11) | t0) * F4 + lane;
    #pragma unroll
    for (int r = 0; r < ROWS_PER_WARP; r++) {
        out[dst_base + r * F4] = v[r];
    }
}

extern "C" void kernel_launch(void* const* d_in, const int* in_sizes, int n_in,
                              void* d_out, int out_size)
{
    const float4* x    = (const float4*)d_in[0];   // (128,1,2048,128) fp32
    const int*    perm = (const int*)   d_in[1];   // (128,)
    const int*    bgn  = (const int*)   d_in[2];   // (128,4)
    const int*    dist = (const int*)   d_in[3];   // (128,4)
    float4*       out  = (float4*)d_out;

    const int groups = 128 * T_DIM / ROWS_PER_WARP;   // 32768
    const int blocks = groups / WARPS_PER_BLK;        // 4096

    cutstripes_kernel<<<blocks, 256>>>(x, perm, bgn, dist, out);
}

// round 13
// speedup vs baseline: 1.0425x; 1.0410x over previous
#include <cuda_runtime.h>

// CutStripes: out[b, :, t, :] = x[perm[b], :, t, :] if t falls inside any of 4
// stripes [bgn[b,s], bgn[b,s]+distance[b,s]), else x[b, :, t, :].
// Shapes: B=128, C=1, T=2048, F=128, STRIPES=4.
//
// FINAL (R13 = R4, the measured wall-time-best: 45.15us wall / regs 32).
// Full lever sweep R2-R12: MLP 1->8 was the only real win (+18%); cp.async,
// cache hints (ld.cs/st.cs), persistent grid, 256-bit accesses, and 8KB page
// groups were all neutral or regressions. All good variants sit at ncu
// 38.2-39.0us = 268 MB mandatory traffic at ~7.0 TB/s combined = 87% of the
// 8 TB/s spec — the mixed read/write HBM turnaround ceiling. No further
// kernel-side lever exists; traffic is irreducible (dense output tensor).

#define T_DIM         2048
#define F4            32        // 128 floats / 4
#define STRIPES       4
#define ROWS_PER_WARP 8
#define WARPS_PER_BLK 8

__global__ __launch_bounds__(256) void cutstripes_kernel(
    const float4* __restrict__ x,
    const int*    __restrict__ perm,
    const int*    __restrict__ bgn,
    const int*    __restrict__ dist,
    float4*       __restrict__ out)
{
    const int warp = (blockIdx.x * blockDim.x + threadIdx.x) >> 5;  // group id
    const int lane = threadIdx.x & 31;

    // Each group = 8 consecutive t rows of one batch b (256 groups per batch).
    const int b  = warp >> 8;
    const int t0 = (warp & 255) * ROWS_PER_WARP;

    // Lane l checks row k=l>>2, stripe s=l&3 -> one ballot covers all 8 rows.
    const int k = lane >> 2;
    const int s = lane & 3;
    const int lo = __ldg(&bgn[b * STRIPES + s]);
    const int hi = lo + __ldg(&dist[b * STRIPES + s]);
    const bool in_stripe = ((t0 + k) >= lo) && ((t0 + k) < hi);
    const unsigned m = __ballot_sync(0xFFFFFFFFu, in_stripe);
    const int pb = __ldg(&perm[b]);

    // 8 independent LDG.128, front-batched (int indexing: max idx < 2^23).
    float4 v[ROWS_PER_WARP];
    #pragma unroll
    for (int r = 0; r < ROWS_PER_WARP; r++) {
        const int src = ((m >> (4 * r)) & 0xF) ? pb : b;
        const int src_idx = ((src << 11) | (t0 + r)) * F4 + lane;
        v[r] = x[src_idx];
    }

    // Streaming stores: evict-first write stream (wall-time-best variant).
    const int dst_base = ((b << 11) | t0) * F4 + lane;
    #pragma unroll
    for (int r = 0; r < ROWS_PER_WARP; r++) {
        __stcs(&out[dst_base + r * F4], v[r]);
    }
}

extern "C" void kernel_launch(void* const* d_in, const int* in_sizes, int n_in,
                              void* d_out, int out_size)
{
    const float4* x    = (const float4*)d_in[0];   // (128,1,2048,128) fp32
    const int*    perm = (const int*)   d_in[1];   // (128,)
    const int*    bgn  = (const int*)   d_in[2];   // (128,4)
    const int*    dist = (const int*)   d_in[3];   // (128,4)
    float4*       out  = (float4*)d_out;

    const int groups = 128 * T_DIM / ROWS_PER_WARP;   // 32768
    const int blocks = groups / WARPS_PER_BLK;        // 4096

    cutstripes_kernel<<<blocks, 256>>>(x, perm, bgn, dist, out);
}